// round 3
// baseline (speedup 1.0000x reference)
#include <cuda_runtime.h>
#include <cstdint>

#define N_NODES 100000
#define N_EDGES 1600000
#define CH      128

// Scratch (static device globals — no allocation in kernel_launch)
__device__ __align__(16) float g_h[(size_t)N_NODES * CH];   // h = x W^T + b  (51.2 MB)
__device__ int   g_deg[N_NODES];
__device__ float g_isd[N_NODES];              // deg^{-1/2}
__device__ int   g_any_hi;                    // nonzero odd word seen => int32 data
__device__ int   g_is64;                      // 1 if edge_index is int64

// ------------------------------------------------------ index dtype sniff ---
// Interpret buffer as int32 words. If dtype is int64, words[2i+1] (high halves)
// are all zero (indices in [0, 100000)). Sample 64k odd words within the first
// 3.2M words (in-bounds for either dtype).
__global__ void k_sniff(const int* __restrict__ w) {
    int t = blockIdx.x * blockDim.x + threadIdx.x;     // 65536 threads
    int i = (int)(((long long)t * 1599983LL) % 1600000LL);  // spread over [0,1.6M)
    if (w[2 * i + 1] != 0) g_any_hi = 1;
}
__global__ void k_sniff_init() { g_any_hi = 0; }
__global__ void k_sniff_fin()  { g_is64 = (g_any_hi == 0); }

__device__ __forceinline__ void edge_params(int* stride, int* dbase) {
    int f = g_is64;
    *stride = f ? 2 : 1;
    *dbase  = f ? 2 * N_EDGES : N_EDGES;
}

// ---------------------------------------------------------------- degree ----
__global__ void k_deg_init() {
    int i = blockIdx.x * blockDim.x + threadIdx.x;
    if (i < N_NODES) g_deg[i] = 1;            // self-loop
}

__global__ void k_deg_count(const int* __restrict__ ei) {
    int e = blockIdx.x * blockDim.x + threadIdx.x;
    if (e >= N_EDGES) return;
    int stride, dbase; edge_params(&stride, &dbase);
    atomicAdd(&g_deg[ei[dbase + stride * e]], 1);
}

__global__ void k_isd() {
    int i = blockIdx.x * blockDim.x + threadIdx.x;
    if (i < N_NODES) g_isd[i] = rsqrtf((float)g_deg[i]);
}

// ------------------------------------------------------------------ GEMM ----
// h[m][o] = b[o] + sum_k x[m][k] * W[o][k]
// 256 threads, 32 rows/block. Warp w -> rows 4w..4w+3; lane j -> cols 4j..4j+3.
__global__ void __launch_bounds__(256) k_gemm(const float* __restrict__ x,
                                              const float* __restrict__ W,
                                              const float* __restrict__ b) {
    __shared__ float xs[32][CH];
    __shared__ float wt[32][CH];   // wt[kk][o] = W[o][kc+kk]

    const int t    = threadIdx.x;
    const int w    = t >> 5;
    const int lane = t & 31;

    const float4* xg = (const float4*)(x + (size_t)blockIdx.x * 32 * CH);
    #pragma unroll
    for (int i = 0; i < 4; i++) {
        int v = t + i * 256;
        ((float4*)&xs[0][0])[v] = xg[v];
    }

    float4 bias = ((const float4*)b)[lane];
    float acc[4][4];
    #pragma unroll
    for (int ri = 0; ri < 4; ri++) {
        acc[ri][0] = bias.x; acc[ri][1] = bias.y;
        acc[ri][2] = bias.z; acc[ri][3] = bias.w;
    }

    const int o    = t & 127;
    const int half = t >> 7;

    for (int kc = 0; kc < CH; kc += 32) {
        __syncthreads();
        #pragma unroll
        for (int i = 0; i < 4; i++) {
            float4 f = *(const float4*)(W + (size_t)o * CH + kc + half * 16 + i * 4);
            int kk = half * 16 + i * 4;
            wt[kk + 0][o] = f.x;
            wt[kk + 1][o] = f.y;
            wt[kk + 2][o] = f.z;
            wt[kk + 3][o] = f.w;
        }
        __syncthreads();

        #pragma unroll
        for (int kk = 0; kk < 32; kk++) {
            float4 bv = *(const float4*)&wt[kk][lane * 4];
            #pragma unroll
            for (int ri = 0; ri < 4; ri++) {
                float a = xs[w * 4 + ri][kc + kk];
                acc[ri][0] += a * bv.x;
                acc[ri][1] += a * bv.y;
                acc[ri][2] += a * bv.z;
                acc[ri][3] += a * bv.w;
            }
        }
    }

    #pragma unroll
    for (int ri = 0; ri < 4; ri++) {
        size_t row = (size_t)blockIdx.x * 32 + w * 4 + ri;
        float4 st = make_float4(acc[ri][0], acc[ri][1], acc[ri][2], acc[ri][3]);
        ((float4*)g_h)[row * 32 + lane] = st;
    }
}

// --------------------------------------------- self-loop init of output ----
// out[i] = h[i] / deg[i]   (self-loop norm = deg^-1/2 * deg^-1/2)
__global__ void k_self(float* __restrict__ out) {
    int idx  = blockIdx.x * blockDim.x + threadIdx.x;   // N*32 threads
    int node = idx >> 5;
    int q    = idx & 31;
    float inv = 1.0f / (float)g_deg[node];
    float4 h  = ((const float4*)g_h)[(size_t)node * 32 + q];
    ((float4*)out)[(size_t)node * 32 + q] =
        make_float4(h.x * inv, h.y * inv, h.z * inv, h.w * inv);
}

// ------------------------------------------------------------ edge scatter --
// One warp per edge: gather h[src] (float4/lane), scale, scalar atomicAdd
// (result unused -> REDG.ADD.F32) into out[dst].
__global__ void __launch_bounds__(256) k_edges(const int* __restrict__ ei,
                                               float* __restrict__ out) {
    int e    = (blockIdx.x << 3) + (threadIdx.x >> 5);
    int lane = threadIdx.x & 31;
    if (e >= N_EDGES) return;

    int stride, dbase; edge_params(&stride, &dbase);
    int s = ei[stride * e];
    int d = ei[dbase + stride * e];
    float nrm = g_isd[s] * g_isd[d];

    float4 h = ((const float4*)g_h)[(size_t)s * 32 + lane];
    float* p = out + (size_t)d * CH + lane * 4;
    atomicAdd(p + 0, h.x * nrm);
    atomicAdd(p + 1, h.y * nrm);
    atomicAdd(p + 2, h.z * nrm);
    atomicAdd(p + 3, h.w * nrm);
}

// ------------------------------------------------------------------- glue ---
extern "C" void kernel_launch(void* const* d_in, const int* in_sizes, int n_in,
                              void* d_out, int out_size) {
    const float* x  = (const float*)d_in[0];
    const int*   ei = (const int*)d_in[1];     // int32 or int64 (sniffed)
    const float* W  = (const float*)d_in[2];
    const float* b  = (const float*)d_in[3];
    float* out = (float*)d_out;

    k_sniff_init<<<1, 1>>>();
    k_sniff<<<256, 256>>>(ei);
    k_sniff_fin<<<1, 1>>>();

    k_deg_init<<<(N_NODES + 255) / 256, 256>>>();
    k_deg_count<<<(N_EDGES + 255) / 256, 256>>>(ei);
    k_gemm<<<N_NODES / 32, 256>>>(x, W, b);      // 100000 % 32 == 0
    k_isd<<<(N_NODES + 255) / 256, 256>>>();
    k_self<<<(N_NODES * 32) / 256, 256>>>(out);  // divisible
    k_edges<<<N_EDGES / 8, 256>>>(ei, out);      // divisible
}

// round 4
// speedup vs baseline: 1.6418x; 1.6418x over previous
#include <cuda_runtime.h>
#include <cstdint>

#define N_NODES 100000
#define N_EDGES 1600000
#define CH      128

// Scratch (static device globals — no allocation in kernel_launch)
__device__ __align__(16) float g_h[(size_t)N_NODES * CH];   // h = x W^T + b  (51.2 MB)
__device__ int   g_deg[N_NODES];
__device__ float g_isd[N_NODES];              // deg^{-1/2}
__device__ int   g_any_hi;                    // nonzero odd word seen => int32 data
__device__ int   g_is64;                      // 1 if edge_index is int64

// ------------------------------------------------------ index dtype sniff ---
__global__ void k_sniff(const int* __restrict__ w) {
    int t = blockIdx.x * blockDim.x + threadIdx.x;     // 65536 threads
    int i = (int)(((long long)t * 1599983LL) % 1600000LL);
    if (w[2 * i + 1] != 0) g_any_hi = 1;
}
__global__ void k_sniff_init() { g_any_hi = 0; }
__global__ void k_sniff_fin()  { g_is64 = (g_any_hi == 0); }

__device__ __forceinline__ void edge_params(int* stride, int* dbase) {
    int f = g_is64;
    *stride = f ? 2 : 1;
    *dbase  = f ? 2 * N_EDGES : N_EDGES;
}

// ---------------------------------------------------------------- degree ----
__global__ void k_deg_init() {
    int i = blockIdx.x * blockDim.x + threadIdx.x;
    if (i < N_NODES) g_deg[i] = 1;            // self-loop
}

__global__ void k_deg_count(const int* __restrict__ ei) {
    int e = blockIdx.x * blockDim.x + threadIdx.x;
    if (e >= N_EDGES) return;
    int stride, dbase; edge_params(&stride, &dbase);
    atomicAdd(&g_deg[ei[dbase + stride * e]], 1);
}

__global__ void k_isd() {
    int i = blockIdx.x * blockDim.x + threadIdx.x;
    if (i < N_NODES) g_isd[i] = rsqrtf((float)g_deg[i]);
}

// ------------------------------------------------------------------ GEMM ----
__global__ void __launch_bounds__(256) k_gemm(const float* __restrict__ x,
                                              const float* __restrict__ W,
                                              const float* __restrict__ b) {
    __shared__ float xs[32][CH];
    __shared__ float wt[32][CH];   // wt[kk][o] = W[o][kc+kk]

    const int t    = threadIdx.x;
    const int w    = t >> 5;
    const int lane = t & 31;

    const float4* xg = (const float4*)(x + (size_t)blockIdx.x * 32 * CH);
    #pragma unroll
    for (int i = 0; i < 4; i++) {
        int v = t + i * 256;
        ((float4*)&xs[0][0])[v] = xg[v];
    }

    float4 bias = ((const float4*)b)[lane];
    float acc[4][4];
    #pragma unroll
    for (int ri = 0; ri < 4; ri++) {
        acc[ri][0] = bias.x; acc[ri][1] = bias.y;
        acc[ri][2] = bias.z; acc[ri][3] = bias.w;
    }

    const int o    = t & 127;
    const int half = t >> 7;

    for (int kc = 0; kc < CH; kc += 32) {
        __syncthreads();
        #pragma unroll
        for (int i = 0; i < 4; i++) {
            float4 f = *(const float4*)(W + (size_t)o * CH + kc + half * 16 + i * 4);
            int kk = half * 16 + i * 4;
            wt[kk + 0][o] = f.x;
            wt[kk + 1][o] = f.y;
            wt[kk + 2][o] = f.z;
            wt[kk + 3][o] = f.w;
        }
        __syncthreads();

        #pragma unroll
        for (int kk = 0; kk < 32; kk++) {
            float4 bv = *(const float4*)&wt[kk][lane * 4];
            #pragma unroll
            for (int ri = 0; ri < 4; ri++) {
                float a = xs[w * 4 + ri][kc + kk];
                acc[ri][0] += a * bv.x;
                acc[ri][1] += a * bv.y;
                acc[ri][2] += a * bv.z;
                acc[ri][3] += a * bv.w;
            }
        }
    }

    #pragma unroll
    for (int ri = 0; ri < 4; ri++) {
        size_t row = (size_t)blockIdx.x * 32 + w * 4 + ri;
        float4 st = make_float4(acc[ri][0], acc[ri][1], acc[ri][2], acc[ri][3]);
        ((float4*)g_h)[row * 32 + lane] = st;
    }
}

// --------------------------------------------- self-loop init of output ----
__global__ void k_self(float* __restrict__ out) {
    int idx  = blockIdx.x * blockDim.x + threadIdx.x;   // N*32 threads
    int node = idx >> 5;
    int q    = idx & 31;
    float inv = 1.0f / (float)g_deg[node];
    float4 h  = ((const float4*)g_h)[(size_t)node * 32 + q];
    ((float4*)out)[(size_t)node * 32 + q] =
        make_float4(h.x * inv, h.y * inv, h.z * inv, h.w * inv);
}

// ------------------------------------------------------------ edge scatter --
// One warp per edge: gather h[src] (float4/lane), scale, vector red.add.v4
// into out[dst] — 4x fewer L2 atomic ops than scalar atomicAdd.
__global__ void __launch_bounds__(256) k_edges(const int* __restrict__ ei,
                                               float* __restrict__ out) {
    int e    = (blockIdx.x << 3) + (threadIdx.x >> 5);
    int lane = threadIdx.x & 31;
    if (e >= N_EDGES) return;

    int stride, dbase; edge_params(&stride, &dbase);
    int s = ei[stride * e];
    int d = ei[dbase + stride * e];
    float nrm = g_isd[s] * g_isd[d];

    float4 h = ((const float4*)g_h)[(size_t)s * 32 + lane];
    float* p = out + (size_t)d * CH + lane * 4;      // 16B aligned
    asm volatile("red.global.add.v4.f32 [%0], {%1, %2, %3, %4};"
                 :: "l"(p), "f"(h.x * nrm), "f"(h.y * nrm),
                    "f"(h.z * nrm), "f"(h.w * nrm)
                 : "memory");
}

// ------------------------------------------------------------------- glue ---
extern "C" void kernel_launch(void* const* d_in, const int* in_sizes, int n_in,
                              void* d_out, int out_size) {
    const float* x  = (const float*)d_in[0];
    const int*   ei = (const int*)d_in[1];     // int32 or int64 (sniffed)
    const float* W  = (const float*)d_in[2];
    const float* b  = (const float*)d_in[3];
    float* out = (float*)d_out;

    k_sniff_init<<<1, 1>>>();
    k_sniff<<<256, 256>>>(ei);
    k_sniff_fin<<<1, 1>>>();

    k_deg_init<<<(N_NODES + 255) / 256, 256>>>();
    k_deg_count<<<(N_EDGES + 255) / 256, 256>>>(ei);
    k_gemm<<<N_NODES / 32, 256>>>(x, W, b);      // 100000 % 32 == 0
    k_isd<<<(N_NODES + 255) / 256, 256>>>();
    k_self<<<(N_NODES * 32) / 256, 256>>>(out);  // divisible
    k_edges<<<N_EDGES / 8, 256>>>(ei, out);      // divisible
}